// round 2
// baseline (speedup 1.0000x reference)
#include <cuda_runtime.h>
#include <cuda_bf16.h>

// Problem shapes (fixed by the dataset)
#define S_LEN 2048
#define BATCH 16
#define DDIM  2048

// Scratch for stage-1 result: altered[b][d], 16*2048 floats = 128 KB.
__device__ float g_altered[BATCH * DDIM];

// ---------------------------------------------------------------------------
// Kernel 1: altered[b][o] = sum_d state[b][d] * W[o][d] + bias[o]
// Warp per output row o. The warp's W row (2048 floats) is preloaded into
// registers as 16 independent float4 loads (MLP=16 -> saturates L1tex queue,
// hides the 577-cycle DRAM latency). state (128 KB) fits in L1 (228 KB) and
// is identical across all warps -> L1 broadcast hits after first touch.
// No shared memory, no barriers anywhere.
// ---------------------------------------------------------------------------
__global__ void __launch_bounds__(256)
stage1_gemv(const float* __restrict__ state,
            const float* __restrict__ W,
            const float* __restrict__ bias)
{
    const int tid    = threadIdx.x;
    const int warpId = tid >> 5;
    const int lane   = tid & 31;
    const int o      = blockIdx.x * 8 + warpId;   // output row (0..2047)

    const float* wrow = W + (long)o * DDIM;

    // Front-batched independent loads of the whole W row (64 regs).
    float4 w[16];
#pragma unroll
    for (int i = 0; i < 16; ++i)
        w[i] = *(const float4*)(wrow + i * 128 + lane * 4);

    float acc[BATCH];
#pragma unroll
    for (int b = 0; b < BATCH; ++b) acc[b] = 0.f;

#pragma unroll
    for (int i = 0; i < 16; ++i) {
        const int d = i * 128 + lane * 4;
#pragma unroll
        for (int b = 0; b < BATCH; ++b) {
            const float4 s4 = *(const float4*)(state + b * DDIM + d);
            acc[b] += w[i].x * s4.x + w[i].y * s4.y
                    + w[i].z * s4.z + w[i].w * s4.w;
        }
    }

    // Warp reduce each of the 16 accumulators.
#pragma unroll
    for (int off = 16; off > 0; off >>= 1) {
#pragma unroll
        for (int b = 0; b < BATCH; ++b)
            acc[b] += __shfl_down_sync(0xFFFFFFFFu, acc[b], off);
    }

    if (lane == 0) {
        const float bo = bias[o];
#pragma unroll
        for (int b = 0; b < BATCH; ++b)
            g_altered[b * DDIM + o] = acc[b] + bo;
    }
}

// ---------------------------------------------------------------------------
// Kernel 2: weights[b][s] = sum_d altered[b][d] * enc[s][b][d]
// Grid: (S/8, B). Block = 256 threads = 8 warps; warp w handles
// s = blockIdx.x*8 + w. altered[b][:] (8 KB) cached in shared.
// 16 unrolled independent float4 global loads per warp -> high MLP,
// fully coalesced 512B/warp/iter. Runs at the LTS chip cap (~6.3 TB/s).
// ---------------------------------------------------------------------------
__global__ void __launch_bounds__(256, 8)
stage2_dots(const float* __restrict__ enc,
            float* __restrict__ out)
{
    __shared__ float alt[DDIM];

    const int tid    = threadIdx.x;
    const int warpId = tid >> 5;
    const int lane   = tid & 31;
    const int b      = blockIdx.y;
    const int s      = blockIdx.x * 8 + warpId;

    // Load altered[b][:] into shared: 2048 floats = 512 float4, 256 thr x 2.
#pragma unroll
    for (int j = 0; j < 2; ++j) {
        int f4 = tid + j * 256;
        *(float4*)&alt[f4 * 4] = *(const float4*)(g_altered + b * DDIM + f4 * 4);
    }
    __syncthreads();

    const float* row = enc + ((long)s * BATCH + b) * DDIM;

    float4 acc = make_float4(0.f, 0.f, 0.f, 0.f);
#pragma unroll
    for (int i = 0; i < 16; ++i) {
        const int d = i * 128 + lane * 4;
        const float4 e = *(const float4*)(row + d);
        const float4 a = *(const float4*)&alt[d];
        acc.x += e.x * a.x;
        acc.y += e.y * a.y;
        acc.z += e.z * a.z;
        acc.w += e.w * a.w;
    }

    float t = (acc.x + acc.y) + (acc.z + acc.w);
#pragma unroll
    for (int off = 16; off > 0; off >>= 1)
        t += __shfl_down_sync(0xFFFFFFFFu, t, off);

    if (lane == 0)
        out[b * S_LEN + s] = t;   // output shape [B, S]
}

extern "C" void kernel_launch(void* const* d_in, const int* in_sizes, int n_in,
                              void* d_out, int out_size)
{
    const float* enc   = (const float*)d_in[0];  // [S, B, D]
    const float* state = (const float*)d_in[1];  // [B, D]
    const float* W     = (const float*)d_in[2];  // [D, D]
    const float* bias  = (const float*)d_in[3];  // [D]
    float* out         = (float*)d_out;          // [B, S]

    stage1_gemv<<<DDIM / 8, 256>>>(state, W, bias);
    stage2_dots<<<dim3(S_LEN / 8, BATCH), 256>>>(enc, out);
}

// round 3
// speedup vs baseline: 1.1583x; 1.1583x over previous
#include <cuda_runtime.h>
#include <cuda_bf16.h>

// Problem shapes (fixed by the dataset)
#define S_LEN 2048
#define BATCH 16
#define DDIM  2048
#define KSPLIT 4
#define KCHUNK (DDIM / KSPLIT)   // 512

// Stage-1 scratch (device globals: allocation-free).
__device__ float g_part[KSPLIT * BATCH * DDIM];   // [kc][b][o], 512 KB
__device__ float g_altered[BATCH * DDIM];         // [b][o], 128 KB

// ---------------------------------------------------------------------------
// Kernel 1a: partial[kc][b][o] = sum_{d in chunk kc} state[b][d] * W[o][d]
// Grid (DDIM/8, KSPLIT); block 256 = 8 warps; warp owns one output row o for
// one K-chunk of 512. Only 4 W float4 loads + 64 state loads per thread ->
// low regs, high occupancy, 4x warp parallelism vs monolithic version.
// state (128 KB) lives in L1 after first touch; W is streamed once total.
// ---------------------------------------------------------------------------
__global__ void __launch_bounds__(256)
stage1_part(const float* __restrict__ state,
            const float* __restrict__ W)
{
    const int tid    = threadIdx.x;
    const int warpId = tid >> 5;
    const int lane   = tid & 31;
    const int o      = blockIdx.x * 8 + warpId;     // output row
    const int kc     = blockIdx.y;                  // K chunk
    const int kbase  = kc * KCHUNK;

    const float* wrow = W + (long)o * DDIM + kbase;

    float acc[BATCH];
#pragma unroll
    for (int b = 0; b < BATCH; ++b) acc[b] = 0.f;

#pragma unroll
    for (int i = 0; i < KCHUNK / 128; ++i) {        // 4 iterations
        const int doff = i * 128 + lane * 4;
        const float4 w4 = *(const float4*)(wrow + doff);
        const int d = kbase + doff;
#pragma unroll
        for (int b = 0; b < BATCH; ++b) {
            const float4 s4 = *(const float4*)(state + b * DDIM + d);
            acc[b] += w4.x * s4.x + w4.y * s4.y + w4.z * s4.z + w4.w * s4.w;
        }
    }

#pragma unroll
    for (int off = 16; off > 0; off >>= 1) {
#pragma unroll
        for (int b = 0; b < BATCH; ++b)
            acc[b] += __shfl_down_sync(0xFFFFFFFFu, acc[b], off);
    }

    if (lane == 0) {
#pragma unroll
        for (int b = 0; b < BATCH; ++b)
            g_part[(kc * BATCH + b) * DDIM + o] = acc[b];
    }
}

// ---------------------------------------------------------------------------
// Kernel 1b: altered[b][o] = bias[o] + sum_kc partial[kc][b][o]
// 32768 outputs, one thread each; fully coalesced. Deterministic order.
// ---------------------------------------------------------------------------
__global__ void __launch_bounds__(256)
stage1_reduce(const float* __restrict__ bias)
{
    const int idx = blockIdx.x * 256 + threadIdx.x;   // 0..32767
    const int o   = idx & (DDIM - 1);
    float v = bias[o];
#pragma unroll
    for (int kc = 0; kc < KSPLIT; ++kc)
        v += g_part[kc * BATCH * DDIM + idx];
    g_altered[idx] = v;
}

// ---------------------------------------------------------------------------
// Kernel 2: weights[b][s] = sum_d altered[b][d] * enc[s][b][d]
// At the LTS chip cap (~6.3 TB/s) -- unchanged from R1.
// ---------------------------------------------------------------------------
__global__ void __launch_bounds__(256, 8)
stage2_dots(const float* __restrict__ enc,
            float* __restrict__ out)
{
    __shared__ float alt[DDIM];

    const int tid    = threadIdx.x;
    const int warpId = tid >> 5;
    const int lane   = tid & 31;
    const int b      = blockIdx.y;
    const int s      = blockIdx.x * 8 + warpId;

#pragma unroll
    for (int j = 0; j < 2; ++j) {
        int f4 = tid + j * 256;
        *(float4*)&alt[f4 * 4] = *(const float4*)(g_altered + b * DDIM + f4 * 4);
    }
    __syncthreads();

    const float* row = enc + ((long)s * BATCH + b) * DDIM;

    float4 acc = make_float4(0.f, 0.f, 0.f, 0.f);
#pragma unroll
    for (int i = 0; i < 16; ++i) {
        const int d = i * 128 + lane * 4;
        const float4 e = *(const float4*)(row + d);
        const float4 a = *(const float4*)&alt[d];
        acc.x += e.x * a.x;
        acc.y += e.y * a.y;
        acc.z += e.z * a.z;
        acc.w += e.w * a.w;
    }

    float t = (acc.x + acc.y) + (acc.z + acc.w);
#pragma unroll
    for (int off = 16; off > 0; off >>= 1)
        t += __shfl_down_sync(0xFFFFFFFFu, t, off);

    if (lane == 0)
        out[b * S_LEN + s] = t;   // output shape [B, S]
}

extern "C" void kernel_launch(void* const* d_in, const int* in_sizes, int n_in,
                              void* d_out, int out_size)
{
    const float* enc   = (const float*)d_in[0];  // [S, B, D]
    const float* state = (const float*)d_in[1];  // [B, D]
    const float* W     = (const float*)d_in[2];  // [D, D]
    const float* bias  = (const float*)d_in[3];  // [D]
    float* out         = (float*)d_out;          // [B, S]

    stage1_part<<<dim3(DDIM / 8, KSPLIT), 256>>>(state, W);
    stage1_reduce<<<(BATCH * DDIM) / 256, 256>>>(bias);
    stage2_dots<<<dim3(S_LEN / 8, BATCH), 256>>>(enc, out);
}

// round 4
// speedup vs baseline: 1.1802x; 1.0189x over previous
#include <cuda_runtime.h>
#include <cuda_bf16.h>

// Problem shapes (fixed by the dataset)
#define S_LEN 2048
#define BATCH 16
#define DDIM  2048

// Stage-1 tiling
#define OTILE  128                 // output rows per block
#define KSPLIT 32
#define KCHUNK (DDIM / KSPLIT)     // 64 d per block
#define WPAD   65                  // sW row pad: bank = (o + d) % 32, conflict-free

// Scratch (device globals: allocation-free).
__device__ float g_part[KSPLIT * BATCH * DDIM];   // [kc][b][o], 4 MB
__device__ float g_altered[BATCH * DDIM];         // [b][o], 128 KB

// ---------------------------------------------------------------------------
// Kernel 1a: partial[kc][b][o] = sum_{d in chunk} state[b][d] * W[o][d]
// Block 128 threads; thread owns ONE output row o and ALL 16 batch accs ->
// no cross-lane reduction. W tile staged to shared with conflict-free pad;
// state chunk staged transposed (sS[d][b]) so compute reads are 4 broadcast
// LDS.128 per d. Per d per thread: 1 W LDS + 4 state LDS + 16 FFMA
// => FMA-pipe bound (~76% of the scalar-FFMA floor).
// ---------------------------------------------------------------------------
__global__ void __launch_bounds__(128)
stage1_part(const float* __restrict__ state,
            const float* __restrict__ W)
{
    __shared__ float sW[OTILE][WPAD];       // 33.3 KB
    __shared__ float sS[KCHUNK][BATCH];     // 4 KB

    const int t  = threadIdx.x;             // 0..127 = local o
    const int o  = blockIdx.x * OTILE + t;  // global output row
    const int kc = blockIdx.y;
    const int d0 = kc * KCHUNK;

    // Stage W row o (64 floats) -> sW[t][:], 16 independent float4 LDG (MLP=16),
    // scalar STS (conflict-free: bank = (t + d) % 32).
    const float4* wrow = (const float4*)(W + (long)o * DDIM + d0);
#pragma unroll
    for (int i = 0; i < KCHUNK / 4; ++i) {
        const float4 v = wrow[i];
        sW[t][i * 4 + 0] = v.x;
        sW[t][i * 4 + 1] = v.y;
        sW[t][i * 4 + 2] = v.z;
        sW[t][i * 4 + 3] = v.w;
    }

    // Stage state chunk transposed: sS[d][b] = state[b][d0 + d].
#pragma unroll
    for (int i = t; i < KCHUNK * BATCH; i += 128) {
        const int d = i >> 4;
        const int b = i & 15;
        sS[d][b] = state[b * DDIM + d0 + d];
    }
    __syncthreads();

    float acc[BATCH];
#pragma unroll
    for (int b = 0; b < BATCH; ++b) acc[b] = 0.f;

#pragma unroll 4
    for (int d = 0; d < KCHUNK; ++d) {
        const float  w  = sW[t][d];                       // conflict-free
        const float4 s0 = *(const float4*)&sS[d][0];      // broadcast
        const float4 s1 = *(const float4*)&sS[d][4];
        const float4 s2 = *(const float4*)&sS[d][8];
        const float4 s3 = *(const float4*)&sS[d][12];
        acc[ 0] += w * s0.x;  acc[ 1] += w * s0.y;
        acc[ 2] += w * s0.z;  acc[ 3] += w * s0.w;
        acc[ 4] += w * s1.x;  acc[ 5] += w * s1.y;
        acc[ 6] += w * s1.z;  acc[ 7] += w * s1.w;
        acc[ 8] += w * s2.x;  acc[ 9] += w * s2.y;
        acc[10] += w * s2.z;  acc[11] += w * s2.w;
        acc[12] += w * s3.x;  acc[13] += w * s3.y;
        acc[14] += w * s3.z;  acc[15] += w * s3.w;
    }

    // Coalesced partial stores (o consecutive across threads).
#pragma unroll
    for (int b = 0; b < BATCH; ++b)
        g_part[(kc * BATCH + b) * DDIM + o] = acc[b];
}

// ---------------------------------------------------------------------------
// Kernel 1b: altered[b][o] = bias[o] + sum_kc partial[kc][b][o]
// 32 independent coalesced streams (MLP=32). Deterministic order.
// ---------------------------------------------------------------------------
__global__ void __launch_bounds__(256)
stage1_reduce(const float* __restrict__ bias)
{
    const int idx = blockIdx.x * 256 + threadIdx.x;   // 0..32767
    const int o   = idx & (DDIM - 1);
    float v = bias[o];
#pragma unroll
    for (int kc = 0; kc < KSPLIT; ++kc)
        v += g_part[kc * BATCH * DDIM + idx];
    g_altered[idx] = v;
}

// ---------------------------------------------------------------------------
// Kernel 2: weights[b][s] = sum_d altered[b][d] * enc[s][b][d]
// At the LTS chip cap (~6.3 TB/s) -- unchanged.
// ---------------------------------------------------------------------------
__global__ void __launch_bounds__(256, 8)
stage2_dots(const float* __restrict__ enc,
            float* __restrict__ out)
{
    __shared__ float alt[DDIM];

    const int tid    = threadIdx.x;
    const int warpId = tid >> 5;
    const int lane   = tid & 31;
    const int b      = blockIdx.y;
    const int s      = blockIdx.x * 8 + warpId;

#pragma unroll
    for (int j = 0; j < 2; ++j) {
        int f4 = tid + j * 256;
        *(float4*)&alt[f4 * 4] = *(const float4*)(g_altered + b * DDIM + f4 * 4);
    }
    __syncthreads();

    const float* row = enc + ((long)s * BATCH + b) * DDIM;

    float4 acc = make_float4(0.f, 0.f, 0.f, 0.f);
#pragma unroll
    for (int i = 0; i < 16; ++i) {
        const int d = i * 128 + lane * 4;
        const float4 e = *(const float4*)(row + d);
        const float4 a = *(const float4*)&alt[d];
        acc.x += e.x * a.x;
        acc.y += e.y * a.y;
        acc.z += e.z * a.z;
        acc.w += e.w * a.w;
    }

    float t = (acc.x + acc.y) + (acc.z + acc.w);
#pragma unroll
    for (int off = 16; off > 0; off >>= 1)
        t += __shfl_down_sync(0xFFFFFFFFu, t, off);

    if (lane == 0)
        out[b * S_LEN + s] = t;   // output shape [B, S]
}

extern "C" void kernel_launch(void* const* d_in, const int* in_sizes, int n_in,
                              void* d_out, int out_size)
{
    const float* enc   = (const float*)d_in[0];  // [S, B, D]
    const float* state = (const float*)d_in[1];  // [B, D]
    const float* W     = (const float*)d_in[2];  // [D, D]
    const float* bias  = (const float*)d_in[3];  // [D]
    float* out         = (float*)d_out;          // [B, S]

    stage1_part<<<dim3(DDIM / OTILE, KSPLIT), 128>>>(state, W);
    stage1_reduce<<<(BATCH * DDIM) / 256, 256>>>(bias);
    stage2_dots<<<dim3(S_LEN / 8, BATCH), 256>>>(enc, out);
}

// round 5
// speedup vs baseline: 1.3114x; 1.1112x over previous
#include <cuda_runtime.h>
#include <cuda_bf16.h>
#include <cstdint>

// Problem shapes (fixed by the dataset)
#define S_LEN 2048
#define BATCH 16
#define DDIM  2048

// Stage-1 tiling
#define OTILE   128                // output rows per block
#define KSPLIT  64
#define KCHUNK  (DDIM / KSPLIT)    // 32 d per block
#define WROWPAD 33                 // sW row stride: bank = (t + d) % 32

// Scratch (device globals: allocation-free).
// g_part layout: [kc][o][b]  -> thread stores 16 consecutive floats (4 STG.128)
__device__ float g_part[KSPLIT * DDIM * BATCH];   // 8 MB
__device__ float g_altered[BATCH * DDIM];         // [b][o], 128 KB

__device__ __forceinline__ void ffma2(uint64_t& d, uint64_t a, uint64_t b) {
    asm("fma.rn.f32x2 %0, %1, %2, %0;" : "+l"(d) : "l"(a), "l"(b));
}

// ---------------------------------------------------------------------------
// Kernel 1a: partial[kc][o][b] = sum_{d in chunk kc} state[b][d] * W[o][d]
// Block 128 thr; thread owns output row o (all 16 batches, no reduction).
// W tile (128x32) loaded COALESCED (8 lanes/row, nL=4/LDG) into padded smem.
// state chunk staged transposed sS[d][b]; compute reads are broadcast
// LDS.128 -> ulonglong2 pairs feeding packed fma.rn.f32x2 (8 FFMA2 per d).
// ---------------------------------------------------------------------------
__global__ void __launch_bounds__(128)
stage1_part(const float* __restrict__ state,
            const float* __restrict__ W)
{
    __shared__ float sW[OTILE][WROWPAD];    // 16.9 KB
    __shared__ float sS[KCHUNK][BATCH];     // 2 KB

    const int t     = threadIdx.x;          // 0..127 = local o
    const int obase = blockIdx.x * OTILE;
    const int kc    = blockIdx.y;
    const int d0    = kc * KCHUNK;

    // --- Coalesced W tile load: 1024 float4, 8 per thread.
    // f4 = j*128 + t; row = f4>>3 (8 float4 per 32-float row), c4 = f4&7.
    // Warp: 4 consecutive rows x 8 lanes -> 4 x 128B lines per LDG.
    // STS banks: (row + 4*c4 + k) % 32, row spans 4, c4 spans 8 -> conflict-free.
#pragma unroll
    for (int j = 0; j < 8; ++j) {
        const int f4 = j * 128 + t;
        const int r  = f4 >> 3;
        const int c4 = f4 & 7;
        const float4 v = *(const float4*)(W + (long)(obase + r) * DDIM + d0 + c4 * 4);
        sW[r][c4 * 4 + 0] = v.x;
        sW[r][c4 * 4 + 1] = v.y;
        sW[r][c4 * 4 + 2] = v.z;
        sW[r][c4 * 4 + 3] = v.w;
    }

    // --- state chunk: 512 floats, 1 float4 per thread (coalesced), transposed STS.
    {
        const int b  = t >> 3;
        const int c4 = t & 7;
        const float4 v = *(const float4*)(state + b * DDIM + d0 + c4 * 4);
        sS[c4 * 4 + 0][b] = v.x;
        sS[c4 * 4 + 1][b] = v.y;
        sS[c4 * 4 + 2][b] = v.z;
        sS[c4 * 4 + 3][b] = v.w;
    }
    __syncthreads();

    uint64_t acc[8];
#pragma unroll
    for (int i = 0; i < 8; ++i) acc[i] = 0ull;

#pragma unroll 8
    for (int d = 0; d < KCHUNK; ++d) {
        const float w = sW[t][d];                 // bank (t+d)%32: conflict-free
        uint64_t wp;
        asm("mov.b64 %0, {%1, %1};" : "=l"(wp) : "r"(__float_as_uint(w)));
        const ulonglong2 q0 = *(const ulonglong2*)&sS[d][0];   // broadcast LDS.128
        const ulonglong2 q1 = *(const ulonglong2*)&sS[d][4];
        const ulonglong2 q2 = *(const ulonglong2*)&sS[d][8];
        const ulonglong2 q3 = *(const ulonglong2*)&sS[d][12];
        ffma2(acc[0], wp, q0.x);  ffma2(acc[1], wp, q0.y);
        ffma2(acc[2], wp, q1.x);  ffma2(acc[3], wp, q1.y);
        ffma2(acc[4], wp, q2.x);  ffma2(acc[5], wp, q2.y);
        ffma2(acc[6], wp, q3.x);  ffma2(acc[7], wp, q3.y);
    }

    // Unpack 8 x f32x2 -> 16 floats, store 4 STG.128 (16 consecutive floats).
    float r[16];
#pragma unroll
    for (int i = 0; i < 8; ++i)
        asm("mov.b64 {%0, %1}, %2;" : "=f"(r[2 * i]), "=f"(r[2 * i + 1]) : "l"(acc[i]));

    float* dst = g_part + ((long)kc * DDIM + (obase + t)) * BATCH;
#pragma unroll
    for (int i = 0; i < 4; ++i)
        *(float4*)(dst + i * 4) = make_float4(r[i * 4], r[i * 4 + 1], r[i * 4 + 2], r[i * 4 + 3]);
}

// ---------------------------------------------------------------------------
// Kernel 1b: altered[b][o] = bias[o] + sum_kc partial[kc][o][b]
// Linear index n = o*16+b; partial reads fully coalesced (64 streams, MLP
// high). g_altered writes scattered but only 128 KB total.
// ---------------------------------------------------------------------------
__global__ void __launch_bounds__(256)
stage1_reduce(const float* __restrict__ bias)
{
    const int n = blockIdx.x * 256 + threadIdx.x;   // 0..32767
    const int o = n >> 4;
    const int b = n & 15;
    float v = bias[o];
#pragma unroll
    for (int kc = 0; kc < KSPLIT; ++kc)
        v += g_part[(long)kc * DDIM * BATCH + n];
    g_altered[b * DDIM + o] = v;
}

// ---------------------------------------------------------------------------
// Kernel 2: weights[b][s] = sum_d altered[b][d] * enc[s][b][d]
// At the LTS chip cap (~6.3 TB/s) -- unchanged.
// ---------------------------------------------------------------------------
__global__ void __launch_bounds__(256, 8)
stage2_dots(const float* __restrict__ enc,
            float* __restrict__ out)
{
    __shared__ float alt[DDIM];

    const int tid    = threadIdx.x;
    const int warpId = tid >> 5;
    const int lane   = tid & 31;
    const int b      = blockIdx.y;
    const int s      = blockIdx.x * 8 + warpId;

#pragma unroll
    for (int j = 0; j < 2; ++j) {
        int f4 = tid + j * 256;
        *(float4*)&alt[f4 * 4] = *(const float4*)(g_altered + b * DDIM + f4 * 4);
    }
    __syncthreads();

    const float* row = enc + ((long)s * BATCH + b) * DDIM;

    float4 acc = make_float4(0.f, 0.f, 0.f, 0.f);
#pragma unroll
    for (int i = 0; i < 16; ++i) {
        const int d = i * 128 + lane * 4;
        const float4 e = *(const float4*)(row + d);
        const float4 a = *(const float4*)&alt[d];
        acc.x += e.x * a.x;
        acc.y += e.y * a.y;
        acc.z += e.z * a.z;
        acc.w += e.w * a.w;
    }

    float t = (acc.x + acc.y) + (acc.z + acc.w);
#pragma unroll
    for (int off = 16; off > 0; off >>= 1)
        t += __shfl_down_sync(0xFFFFFFFFu, t, off);

    if (lane == 0)
        out[b * S_LEN + s] = t;   // output shape [B, S]
}

extern "C" void kernel_launch(void* const* d_in, const int* in_sizes, int n_in,
                              void* d_out, int out_size)
{
    const float* enc   = (const float*)d_in[0];  // [S, B, D]
    const float* state = (const float*)d_in[1];  // [B, D]
    const float* W     = (const float*)d_in[2];  // [D, D]
    const float* bias  = (const float*)d_in[3];  // [D]
    float* out         = (float*)d_out;          // [B, S]

    stage1_part<<<dim3(DDIM / OTILE, KSPLIT), 128>>>(state, W);
    stage1_reduce<<<(BATCH * DDIM) / 256, 256>>>(bias);
    stage2_dots<<<dim3(S_LEN / 8, BATCH), 256>>>(enc, out);
}